// round 1
// baseline (speedup 1.0000x reference)
#include <cuda_runtime.h>
#include <math.h>

// DGPLoss: fused 5x5-patch depth-guided propagation loss.
//   seg_feat: [4, 64, 512, 512] fp32   (d_in[0])
//   dep_true: [4, 1, 512, 512]  fp32   (d_in[1])
//   out: scalar fp32 mean over masked loss terms.
//
// Patches: non-overlapping 5x5, 102x102 patches -> pixels h,w in [0,510).
// Per pixel: seg_sq = sum_c (seg[c, center] - seg[c, pixel])^2
//            dep_diff = |dep[center] - dep[pixel]|
//            loss = exp(-dep_diff/10) * exp(-seg_sq)
//            mask = dep_diff>eps && sqrt(seg_sq)>eps && dep[pixel]>eps && !is_center
// Output = sum(mask*loss) / max(count(mask), 1)

#define EPSF 1e-8f
#define CS   262144            // 512*512 channel (and dep batch) stride
#define GX   4
#define GY   510
#define GZ   4
#define NBLK (GX * GY * GZ)    // 8160 blocks

// Deterministic two-pass reduction scratch (no atomics, no allocation).
__device__ float g_psum[NBLK];
__device__ int   g_pcnt[NBLK];

__global__ __launch_bounds__(128, 8)
void dgp_main(const float* __restrict__ seg, const float* __restrict__ dep) {
    const int w = blockIdx.x * 128 + threadIdx.x;
    const int h = blockIdx.y;
    const int b = blockIdx.z;

    float loss = 0.0f;
    int   cnt  = 0;

    if (w < 510) {
        const int hc = (h / 5) * 5 + 2;
        const int wc = (w / 5) * 5 + 2;

        const int segBase = b * 64 * CS;          // fits in int32 (max ~6.7e7)
        const float* __restrict__ pix = seg + segBase + h  * 512 + w;
        const float* __restrict__ ctr = seg + segBase + hc * 512 + wc;

        // 64-channel accumulation; unroll for memory-level parallelism.
        float acc = 0.0f;
        #pragma unroll 16
        for (int c = 0; c < 64; ++c) {
            const float p = pix[c * CS];
            const float q = ctr[c * CS];
            const float d = q - p;
            acc = fmaf(d, d, acc);
        }

        const int   depBase = b * CS;
        const float dp = dep[depBase + h  * 512 + w];
        const float dc = dep[depBase + hc * 512 + wc];
        const float ddiff = fabsf(dc - dp);

        // Match reference: two separate fp32 exps, multiplied.
        const float l = __expf(-ddiff * 0.1f) * __expf(-acc);

        const bool is_center = (h == hc) && (w == wc);
        const bool m = (ddiff > EPSF) && (sqrtf(acc) > EPSF) && (dp > EPSF) && !is_center;
        if (m) { loss = l; cnt = 1; }
    }

    // Intra-warp reduce
    #pragma unroll
    for (int o = 16; o > 0; o >>= 1) {
        loss += __shfl_down_sync(0xFFFFFFFFu, loss, o);
        cnt  += __shfl_down_sync(0xFFFFFFFFu, cnt,  o);
    }

    __shared__ float ss[4];
    __shared__ int   sc[4];
    const int lane = threadIdx.x & 31;
    const int wid  = threadIdx.x >> 5;
    if (lane == 0) { ss[wid] = loss; sc[wid] = cnt; }
    __syncthreads();

    if (threadIdx.x == 0) {
        const float s = ss[0] + ss[1] + ss[2] + ss[3];
        const int   c = sc[0] + sc[1] + sc[2] + sc[3];
        const int blk = blockIdx.x + GX * (blockIdx.y + GY * blockIdx.z);
        g_psum[blk] = s;
        g_pcnt[blk] = c;
    }
}

__global__ __launch_bounds__(256)
void dgp_reduce(float* __restrict__ out) {
    __shared__ float ss[256];
    __shared__ int   sc[256];

    float s = 0.0f;
    int   c = 0;
    for (int i = threadIdx.x; i < NBLK; i += 256) {
        s += g_psum[i];
        c += g_pcnt[i];
    }
    ss[threadIdx.x] = s;
    sc[threadIdx.x] = c;
    __syncthreads();

    #pragma unroll
    for (int stride = 128; stride > 0; stride >>= 1) {
        if (threadIdx.x < stride) {
            ss[threadIdx.x] += ss[threadIdx.x + stride];
            sc[threadIdx.x] += sc[threadIdx.x + stride];
        }
        __syncthreads();
    }

    if (threadIdx.x == 0) {
        const int n = sc[0] > 1 ? sc[0] : 1;
        out[0] = ss[0] / (float)n;
    }
}

extern "C" void kernel_launch(void* const* d_in, const int* in_sizes, int n_in,
                              void* d_out, int out_size) {
    const float* seg = (const float*)d_in[0];   // [4,64,512,512]
    const float* dep = (const float*)d_in[1];   // [4,1,512,512]
    float* out = (float*)d_out;

    dim3 grid(GX, GY, GZ);
    dgp_main<<<grid, 128>>>(seg, dep);
    dgp_reduce<<<1, 256>>>(out);
}

// round 2
// speedup vs baseline: 1.1641x; 1.1641x over previous
#include <cuda_runtime.h>
#include <math.h>

// DGPLoss fused single-kernel:
//   seg_feat: [4, 64, 512, 512] fp32   (d_in[0])
//   dep_true: [4, 1, 512, 512]  fp32   (d_in[1])
//   out[0]  : scalar fp32
//
// Per pixel (h,w in [0,510)): seg_sq = sum_c (seg[c,ctr]-seg[c,pix])^2
//   loss = exp(-(|dep_ctr-dep_pix|/10 + seg_sq))
//   mask = ddiff>1e-8 && seg_sq>1e-16 && dep_pix>1e-8 && !is_center
// out = sum(mask*loss) / max(count,1)
//
// One thread = 4 horizontally-adjacent pixels (LDG.128); a 4-pixel quad spans
// at most 2 patches -> 2 center scalar loads per channel. Last block (ticket)
// does the final deterministic fixed-order reduction over 2040 partials.

#define EPSF 1e-8f
#define EPS2 1e-16f
#define CS   262144           // 512*512
#define NH   510
#define NBAT 4
#define NPART (NH * NBAT)     // 2040 blocks

__device__ float2       g_part[NPART];
__device__ unsigned int g_ticket;     // zero-init; reset by last block each run

__global__ __launch_bounds__(128)
void dgp_fused(const float* __restrict__ seg, const float* __restrict__ dep,
               float* __restrict__ out)
{
    const int tid = threadIdx.x;
    const int h   = blockIdx.x;          // 0..509
    const int b   = blockIdx.y;          // 0..3
    const int w0  = tid << 2;            // 0,4,...,508

    const int hc  = (h / 5) * 5 + 2;
    const int pA  = w0 / 5;
    const int pB  = (w0 + 3) / 5;
    const int wcA = pA * 5 + 2;
    const int wcB = pB * 5 + 2;
    const bool sB1 = ((w0 + 1) / 5) != pA;
    const bool sB2 = ((w0 + 2) / 5) != pA;
    const bool sB3 = (pB != pA);

    const int segBase = b * (64 * CS);   // max ~50.3M, fits int32
    const int rowOff  = h  * 512 + w0;
    const int cOffA   = hc * 512 + wcA;
    const int cOffB   = hc * 512 + wcB;

    const float4* __restrict__ pix = (const float4*)(seg + segBase + rowOff);
    const float*  __restrict__ ctA = seg + segBase + cOffA;
    const float*  __restrict__ ctB = seg + segBase + cOffB;

    float a0 = 0.f, a1 = 0.f, a2 = 0.f, a3 = 0.f;
    #pragma unroll 8
    for (int c = 0; c < 64; ++c) {
        const float4 p  = pix[c * (CS / 4)];
        const float  qA = ctA[c * CS];
        const float  qB = ctB[c * CS];
        const float  q1 = sB1 ? qB : qA;
        const float  q2 = sB2 ? qB : qA;
        const float  q3 = sB3 ? qB : qA;
        float d;
        d = qA - p.x; a0 = fmaf(d, d, a0);
        d = q1 - p.y; a1 = fmaf(d, d, a1);
        d = q2 - p.z; a2 = fmaf(d, d, a2);
        d = q3 - p.w; a3 = fmaf(d, d, a3);
    }

    const int depBase = b * CS;
    const float4 dp  = *(const float4*)(dep + depBase + rowOff);
    const float  dcA = dep[depBase + cOffA];
    const float  dcB = dep[depBase + cOffB];
    const float  dc1 = sB1 ? dcB : dcA;
    const float  dc2 = sB2 ? dcB : dcA;
    const float  dc3 = sB3 ? dcB : dcA;

    float sum = 0.f, cnt = 0.f;
    {
        const float dd = fabsf(dcA - dp.x);
        const bool ic  = (h == hc) && (w0 == wcA);
        const bool m   = (dd > EPSF) && (a0 > EPS2) && (dp.x > EPSF) && !ic && (w0 < 510);
        const float l  = __expf(-fmaf(dd, 0.1f, a0));
        if (m) { sum += l; cnt += 1.f; }
    }
    {
        const int  wc  = sB1 ? wcB : wcA;
        const float dd = fabsf(dc1 - dp.y);
        const bool ic  = (h == hc) && (w0 + 1 == wc);
        const bool m   = (dd > EPSF) && (a1 > EPS2) && (dp.y > EPSF) && !ic && (w0 + 1 < 510);
        const float l  = __expf(-fmaf(dd, 0.1f, a1));
        if (m) { sum += l; cnt += 1.f; }
    }
    {
        const int  wc  = sB2 ? wcB : wcA;
        const float dd = fabsf(dc2 - dp.z);
        const bool ic  = (h == hc) && (w0 + 2 == wc);
        const bool m   = (dd > EPSF) && (a2 > EPS2) && (dp.z > EPSF) && !ic && (w0 + 2 < 510);
        const float l  = __expf(-fmaf(dd, 0.1f, a2));
        if (m) { sum += l; cnt += 1.f; }
    }
    {
        const int  wc  = sB3 ? wcB : wcA;
        const float dd = fabsf(dc3 - dp.w);
        const bool ic  = (h == hc) && (w0 + 3 == wc);
        const bool m   = (dd > EPSF) && (a3 > EPS2) && (dp.w > EPSF) && !ic && (w0 + 3 < 510);
        const float l  = __expf(-fmaf(dd, 0.1f, a3));
        if (m) { sum += l; cnt += 1.f; }
    }

    // intra-warp reduce
    #pragma unroll
    for (int o = 16; o > 0; o >>= 1) {
        sum += __shfl_down_sync(0xFFFFFFFFu, sum, o);
        cnt += __shfl_down_sync(0xFFFFFFFFu, cnt, o);
    }

    __shared__ float2 sw[4];
    __shared__ bool   isLast;
    const int lane = tid & 31;
    const int wid  = tid >> 5;
    if (lane == 0) sw[wid] = make_float2(sum, cnt);
    __syncthreads();

    if (tid == 0) {
        const float2 t0 = sw[0], t1 = sw[1], t2 = sw[2], t3 = sw[3];
        g_part[blockIdx.x + NH * blockIdx.y] =
            make_float2(t0.x + t1.x + t2.x + t3.x, t0.y + t1.y + t2.y + t3.y);
        __threadfence();
        const unsigned t = atomicAdd(&g_ticket, 1u);
        isLast = (t == NPART - 1);
    }
    __syncthreads();

    if (isLast) {
        __threadfence();
        float s = 0.f, c = 0.f;
        #pragma unroll 4
        for (int i = tid; i < NPART; i += 128) {
            const float2 v = g_part[i];
            s += v.x; c += v.y;
        }
        #pragma unroll
        for (int o = 16; o > 0; o >>= 1) {
            s += __shfl_down_sync(0xFFFFFFFFu, s, o);
            c += __shfl_down_sync(0xFFFFFFFFu, c, o);
        }
        if (lane == 0) sw[wid] = make_float2(s, c);
        __syncthreads();
        if (tid == 0) {
            const float2 t0 = sw[0], t1 = sw[1], t2 = sw[2], t3 = sw[3];
            const float ts = t0.x + t1.x + t2.x + t3.x;
            const float tc = t0.y + t1.y + t2.y + t3.y;
            out[0] = ts / fmaxf(tc, 1.0f);
            g_ticket = 0u;                 // reset for next graph replay
        }
    }
}

extern "C" void kernel_launch(void* const* d_in, const int* in_sizes, int n_in,
                              void* d_out, int out_size) {
    const float* seg = (const float*)d_in[0];   // [4,64,512,512]
    const float* dep = (const float*)d_in[1];   // [4,1,512,512]
    float* out = (float*)d_out;

    dim3 grid(NH, NBAT);
    dgp_fused<<<grid, 128>>>(seg, dep, out);
}